// round 5
// baseline (speedup 1.0000x reference)
#include <cuda_runtime.h>

#define BB 8
#define SS 2048
#define DD 768
#define NSP 512
#define MAXW 30
#define HH 100
#define M_TOTAL (BB*NSP)   /* 4096 */

__device__ float g_att[(size_t)M_TOTAL*DD];

__device__ __forceinline__ unsigned long long f32x2_pack(float x, float y) {
    unsigned long long r;
    asm("mov.b64 %0, {%1, %2};" : "=l"(r) : "r"(__float_as_uint(x)), "r"(__float_as_uint(y)));
    return r;
}
__device__ __forceinline__ void f32x2_fma(unsigned long long& acc,
                                          unsigned long long a, unsigned long long b) {
    asm("fma.rn.f32x2 %0, %1, %2, %0;" : "+l"(acc) : "l"(a), "l"(b));
}
__device__ __forceinline__ float2 f32x2_unpack(unsigned long long v) {
    unsigned int lo, hi;
    asm("mov.b64 {%0, %1}, %2;" : "=r"(lo), "=r"(hi) : "l"(v));
    return make_float2(__uint_as_float(lo), __uint_as_float(hi));
}

// ---- Fused kernel: per-span logits + softmax + weighted sum -------------------
// grid = 4096 (one block per span), 192 threads (one float4 column of D each).
// Pass 1 streams the span rows once (computing partial logit dots, warming L1),
// block-reduce + warp softmax, pass 2 re-reads rows from L1 for the weighted sum.
// att_b is omitted: softmax is invariant to a constant logit shift.
__global__ void __launch_bounds__(192) k_span(const float* __restrict__ seq,
                                              const int* __restrict__ spans,
                                              const int* __restrict__ mask,
                                              const float* __restrict__ att_w) {
    __shared__ float s_part[MAXW][200];   // [w][tid], padded stride avoids aliasing
    __shared__ float s_logit[32];
    __shared__ float s_attn[MAXW];

    int sp   = blockIdx.x;
    int b    = sp >> 9;
    int tid  = threadIdx.x;
    int warp = tid >> 5, lane = tid & 31;

    int start = __ldg(&spans[sp * 2]);
    int cnt   = __ldg(&spans[sp * 2 + 1]) - start;    // width 1..30

    float4 wv = ((const float4*)att_w)[tid];
    const float4* base = (const float4*)seq + (size_t)(b * SS + start) * (DD / 4) + tid;

    // Pass 1: partial logit dots (also warms L1 with the span rows)
    for (int w = 0; w < cnt; w++) {
        float4 v = base[(size_t)w * (DD / 4)];
        s_part[w][tid] = v.x * wv.x + v.y * wv.y + v.z * wv.z + v.w * wv.w;
    }
    __syncthreads();

    // Block reduction: 6 warps, warp k reduces w = k, k+6, ...
    for (int w = warp; w < cnt; w += 6) {
        float s = 0.f;
#pragma unroll
        for (int i = 0; i < 6; i++) s += s_part[w][lane + 32 * i];
#pragma unroll
        for (int o = 16; o > 0; o >>= 1) s += __shfl_xor_sync(0xffffffffu, s, o);
        if (lane == 0) s_logit[w] = s;
    }
    __syncthreads();

    // Warp 0: masked softmax over width + span_mask scale
    if (warp == 0) {
        float lg = (lane < cnt) ? s_logit[lane] : -1e30f;
        float mx = lg;
#pragma unroll
        for (int o = 16; o > 0; o >>= 1) mx = fmaxf(mx, __shfl_xor_sync(0xffffffffu, mx, o));
        float ex = (lane < cnt) ? expf(lg - mx) : 0.f;
        float sm = ex;
#pragma unroll
        for (int o = 16; o > 0; o >>= 1) sm += __shfl_xor_sync(0xffffffffu, sm, o);
        float mk = (float)__ldg(&mask[sp]);
        if (lane < MAXW) s_attn[lane] = ex / sm * mk;
    }
    __syncthreads();

    // Pass 2: weighted sum (rows are L1-hot)
    float4 acc = make_float4(0.f, 0.f, 0.f, 0.f);
#pragma unroll 4
    for (int w = 0; w < cnt; w++) {
        float a  = s_attn[w];
        float4 v = base[(size_t)w * (DD / 4)];
        acc.x += a * v.x; acc.y += a * v.y; acc.z += a * v.z; acc.w += a * v.w;
    }
    ((float4*)g_att)[(size_t)sp * (DD / 4) + tid] = acc;
}

// ---------------- GEMM + bias + tanh (f32x2 packed FMA) ------------------------
#define KC 32
#define NA_F4 ((32*KC)/4)    /* 256 A float4 per chunk  */
#define NW_F4 ((KC*HH)/4)    /* 800 W float4 per chunk  */

__global__ void __launch_bounds__(224) k_gemm(const float* __restrict__ W,
                                              const float* __restrict__ bias,
                                              float* __restrict__ out) {
    __shared__ float sA[KC][36];     // [kk][row]
    __shared__ float sW[KC][100];
    __shared__ float sB[HH];

    int m0  = blockIdx.x * 32;
    int tid = threadIdx.x;

    if (tid < HH) sB[tid] = bias[tid];

    int ai0 = tid, ai1 = tid + 224;
    int wi0 = tid, wi1 = tid + 224, wi2 = tid + 448, wi3 = tid + 672;

    float4 ra0, ra1, rw0, rw1, rw2, rw3;

    const float4* A4 = (const float4*)g_att;
    const float4* W4 = (const float4*)W;

    {
        int k0 = 0;
        if (ai0 < NA_F4) { int r = ai0 >> 3, kf = ai0 & 7; ra0 = A4[(size_t)(m0 + r) * (DD/4) + (k0>>2) + kf]; }
        if (ai1 < NA_F4) { int r = ai1 >> 3, kf = ai1 & 7; ra1 = A4[(size_t)(m0 + r) * (DD/4) + (k0>>2) + kf]; }
        if (wi0 < NW_F4) { int kk = wi0 / 25, c = wi0 % 25; rw0 = W4[(size_t)(k0 + kk) * (HH/4) + c]; }
        if (wi1 < NW_F4) { int kk = wi1 / 25, c = wi1 % 25; rw1 = W4[(size_t)(k0 + kk) * (HH/4) + c]; }
        if (wi2 < NW_F4) { int kk = wi2 / 25, c = wi2 % 25; rw2 = W4[(size_t)(k0 + kk) * (HH/4) + c]; }
        if (wi3 < NW_F4) { int kk = wi3 / 25, c = wi3 % 25; rw3 = W4[(size_t)(k0 + kk) * (HH/4) + c]; }
    }

    unsigned long long accP[4][2];
#pragma unroll
    for (int i = 0; i < 4; i++) { accP[i][0] = 0ull; accP[i][1] = 0ull; }

    int rg = tid / 25, cg = tid % 25;
    int rr = rg * 4,  cc = cg * 4;
    bool active = (tid < 200);

    for (int kc = 0; kc < DD; kc += KC) {
        if (ai0 < NA_F4) { int r = ai0 >> 3, kf = (ai0 & 7) * 4;
            sA[kf+0][r] = ra0.x; sA[kf+1][r] = ra0.y; sA[kf+2][r] = ra0.z; sA[kf+3][r] = ra0.w; }
        if (ai1 < NA_F4) { int r = ai1 >> 3, kf = (ai1 & 7) * 4;
            sA[kf+0][r] = ra1.x; sA[kf+1][r] = ra1.y; sA[kf+2][r] = ra1.z; sA[kf+3][r] = ra1.w; }
        if (wi0 < NW_F4) { int kk = wi0 / 25, c = (wi0 % 25) * 4; *(float4*)&sW[kk][c] = rw0; }
        if (wi1 < NW_F4) { int kk = wi1 / 25, c = (wi1 % 25) * 4; *(float4*)&sW[kk][c] = rw1; }
        if (wi2 < NW_F4) { int kk = wi2 / 25, c = (wi2 % 25) * 4; *(float4*)&sW[kk][c] = rw2; }
        if (wi3 < NW_F4) { int kk = wi3 / 25, c = (wi3 % 25) * 4; *(float4*)&sW[kk][c] = rw3; }
        __syncthreads();

        int kn = kc + KC;
        if (kn < DD) {
            if (ai0 < NA_F4) { int r = ai0 >> 3, kf = ai0 & 7; ra0 = A4[(size_t)(m0 + r) * (DD/4) + (kn>>2) + kf]; }
            if (ai1 < NA_F4) { int r = ai1 >> 3, kf = ai1 & 7; ra1 = A4[(size_t)(m0 + r) * (DD/4) + (kn>>2) + kf]; }
            if (wi0 < NW_F4) { int kk = wi0 / 25, c = wi0 % 25; rw0 = W4[(size_t)(kn + kk) * (HH/4) + c]; }
            if (wi1 < NW_F4) { int kk = wi1 / 25, c = wi1 % 25; rw1 = W4[(size_t)(kn + kk) * (HH/4) + c]; }
            if (wi2 < NW_F4) { int kk = wi2 / 25, c = wi2 % 25; rw2 = W4[(size_t)(kn + kk) * (HH/4) + c]; }
            if (wi3 < NW_F4) { int kk = wi3 / 25, c = wi3 % 25; rw3 = W4[(size_t)(kn + kk) * (HH/4) + c]; }
        }

        if (active) {
#pragma unroll
            for (int kk = 0; kk < KC; kk++) {
                float4 a = *(const float4*)&sA[kk][rr];
                float4 w = *(const float4*)&sW[kk][cc];
                unsigned long long w01 = f32x2_pack(w.x, w.y);
                unsigned long long w23 = f32x2_pack(w.z, w.w);
                float av[4] = {a.x, a.y, a.z, a.w};
#pragma unroll
                for (int i = 0; i < 4; i++) {
                    unsigned long long ad = f32x2_pack(av[i], av[i]);
                    f32x2_fma(accP[i][0], ad, w01);
                    f32x2_fma(accP[i][1], ad, w23);
                }
            }
        }
        __syncthreads();
    }

    if (active) {
#pragma unroll
        for (int i = 0; i < 4; i++) {
            float2 p0 = f32x2_unpack(accP[i][0]);
            float2 p1 = f32x2_unpack(accP[i][1]);
            float4 v;
            v.x = tanhf(p0.x + sB[cc + 0]);
            v.y = tanhf(p0.y + sB[cc + 1]);
            v.z = tanhf(p1.x + sB[cc + 2]);
            v.w = tanhf(p1.y + sB[cc + 3]);
            *(float4*)&out[(size_t)(m0 + rr + i) * HH + cc] = v;
        }
    }
}

extern "C" void kernel_launch(void* const* d_in, const int* in_sizes, int n_in,
                              void* d_out, int out_size) {
    const float* seq   = (const float*)d_in[0];
    const int*   spans = (const int*)d_in[1];
    const int*   mask  = (const int*)d_in[2];
    const float* att_w = (const float*)d_in[3];
    const float* ffn_w = (const float*)d_in[5];
    const float* ffn_b = (const float*)d_in[6];
    float*       out   = (float*)d_out;

    k_span<<<M_TOTAL, 192>>>(seq, spans, mask, att_w);
    k_gemm<<<128, 224>>>(ffn_w, ffn_b, out);
}

// round 6
// speedup vs baseline: 1.1402x; 1.1402x over previous
#include <cuda_runtime.h>

#define BB 8
#define SS 2048
#define DD 768
#define NSP 512
#define MAXW 30
#define HH 100
#define M_TOTAL (BB*NSP)   /* 4096 */

__device__ float g_logits[BB*SS];
__device__ float g_att[(size_t)M_TOTAL*DD];

__device__ __forceinline__ unsigned long long f32x2_pack(float x, float y) {
    unsigned long long r;
    asm("mov.b64 %0, {%1, %2};" : "=l"(r) : "r"(__float_as_uint(x)), "r"(__float_as_uint(y)));
    return r;
}
__device__ __forceinline__ void f32x2_fma(unsigned long long& acc,
                                          unsigned long long a, unsigned long long b) {
    asm("fma.rn.f32x2 %0, %1, %2, %0;" : "+l"(acc) : "l"(a), "l"(b));
}
__device__ __forceinline__ float2 f32x2_unpack(unsigned long long v) {
    unsigned int lo, hi;
    asm("mov.b64 {%0, %1}, %2;" : "=r"(lo), "=r"(hi) : "l"(v));
    return make_float2(__uint_as_float(lo), __uint_as_float(hi));
}

// ---------------- Kernel 1: attention logits, 2 rows/warp, batched loads -------
__global__ void __launch_bounds__(256) k_logits(const float* __restrict__ seq,
                                                const float* __restrict__ att_w,
                                                const float* __restrict__ att_b) {
    __shared__ float sw[DD];
    int tid = threadIdx.x;
    for (int i = tid; i < DD; i += 256) sw[i] = att_w[i];
    __syncthreads();
    int warp = tid >> 5, lane = tid & 31;

    float4 wreg[6];
    const float4* w4 = (const float4*)sw;
#pragma unroll
    for (int j = 0; j < 6; j++) wreg[j] = w4[lane + 32 * j];

    int p0 = (blockIdx.x * 8 + warp) * 2;
    const float4* r0 = (const float4*)(seq + (size_t)p0 * DD);
    const float4* r1 = (const float4*)(seq + (size_t)(p0 + 1) * DD);

    // front-batch all 12 loads for max MLP
    float4 x0 = r0[lane], x1 = r0[lane+32], x2 = r0[lane+64],
           x3 = r0[lane+96], x4 = r0[lane+128], x5 = r0[lane+160];
    float4 y0 = r1[lane], y1 = r1[lane+32], y2 = r1[lane+64],
           y3 = r1[lane+96], y4 = r1[lane+128], y5 = r1[lane+160];

    float s0 = 0.f, s1 = 0.f;
    s0 += x0.x*wreg[0].x + x0.y*wreg[0].y + x0.z*wreg[0].z + x0.w*wreg[0].w;
    s1 += y0.x*wreg[0].x + y0.y*wreg[0].y + y0.z*wreg[0].z + y0.w*wreg[0].w;
    s0 += x1.x*wreg[1].x + x1.y*wreg[1].y + x1.z*wreg[1].z + x1.w*wreg[1].w;
    s1 += y1.x*wreg[1].x + y1.y*wreg[1].y + y1.z*wreg[1].z + y1.w*wreg[1].w;
    s0 += x2.x*wreg[2].x + x2.y*wreg[2].y + x2.z*wreg[2].z + x2.w*wreg[2].w;
    s1 += y2.x*wreg[2].x + y2.y*wreg[2].y + y2.z*wreg[2].z + y2.w*wreg[2].w;
    s0 += x3.x*wreg[3].x + x3.y*wreg[3].y + x3.z*wreg[3].z + x3.w*wreg[3].w;
    s1 += y3.x*wreg[3].x + y3.y*wreg[3].y + y3.z*wreg[3].z + y3.w*wreg[3].w;
    s0 += x4.x*wreg[4].x + x4.y*wreg[4].y + x4.z*wreg[4].z + x4.w*wreg[4].w;
    s1 += y4.x*wreg[4].x + y4.y*wreg[4].y + y4.z*wreg[4].z + y4.w*wreg[4].w;
    s0 += x5.x*wreg[5].x + x5.y*wreg[5].y + x5.z*wreg[5].z + x5.w*wreg[5].w;
    s1 += y5.x*wreg[5].x + y5.y*wreg[5].y + y5.z*wreg[5].z + y5.w*wreg[5].w;

#pragma unroll
    for (int o = 16; o > 0; o >>= 1) {
        s0 += __shfl_xor_sync(0xffffffffu, s0, o);
        s1 += __shfl_xor_sync(0xffffffffu, s1, o);
    }
    if (lane == 0) {
        float b = att_b[0];
        g_logits[p0]     = s0 + b;
        g_logits[p0 + 1] = s1 + b;
    }
}

// ---------------- Kernel 2: per-span softmax + weighted sum (seq L2-hot) -------
__global__ void k_span(const float* __restrict__ seq,
                       const int* __restrict__ spans,
                       const int* __restrict__ mask) {
    __shared__ float s_attn[MAXW];
    __shared__ int   s_start, s_cnt;
    int sp  = blockIdx.x;
    int b   = sp >> 9;
    int tid = threadIdx.x;

    if (tid < 32) {
        int start = spans[sp * 2];
        int cnt   = spans[sp * 2 + 1] - start;        // width 1..30
        float lg = (tid < cnt) ? g_logits[b * SS + start + tid] : -1e30f;
        float mx = lg;
#pragma unroll
        for (int o = 16; o > 0; o >>= 1) mx = fmaxf(mx, __shfl_xor_sync(0xffffffffu, mx, o));
        float ex = (tid < cnt) ? expf(lg - mx) : 0.f;
        float sm = ex;
#pragma unroll
        for (int o = 16; o > 0; o >>= 1) sm += __shfl_xor_sync(0xffffffffu, sm, o);
        float mk = (float)mask[sp];
        if (tid < MAXW) s_attn[tid] = ex / sm * mk;
        if (tid == 0) { s_start = start; s_cnt = cnt; }
    }
    __syncthreads();

    int start = s_start, cnt = s_cnt;
    const float4* base = (const float4*)seq + (size_t)(b * SS + start) * (DD / 4) + tid;
    float4 acc = make_float4(0.f, 0.f, 0.f, 0.f);
#pragma unroll 4
    for (int w = 0; w < cnt; w++) {
        float a  = s_attn[w];
        float4 v = base[(size_t)w * (DD / 4)];
        acc.x += a * v.x; acc.y += a * v.y; acc.z += a * v.z; acc.w += a * v.w;
    }
    ((float4*)g_att)[(size_t)sp * (DD / 4) + tid] = acc;
}

// -------- Kernel 3: GEMM + bias + tanh, in-block split-K=2, f32x2 FMA ----------
// grid = 128 (M-tile 32), block = 448: warps 0-6 -> K[0:384), warps 7-13 -> K[384:768)
#define KC 32
#define NA_F4 ((32*KC)/4)    /* 256 */
#define NW_F4 ((KC*HH)/4)    /* 800 */

__global__ void __launch_bounds__(448) k_gemm(const float* __restrict__ W,
                                              const float* __restrict__ bias,
                                              float* __restrict__ out) {
    __shared__ float sA[2][KC][36];
    __shared__ float sW[2][KC][100];
    __shared__ float sB[HH];

    int m0   = blockIdx.x * 32;
    int tid  = threadIdx.x;
    int half = tid / 224;        // 0 or 1
    int htid = tid % 224;
    int kb   = half * 384;       // this half's K base

    if (tid < HH) sB[tid] = bias[tid];

    int ai0 = htid, ai1 = htid + 224;
    int wi0 = htid, wi1 = htid + 224, wi2 = htid + 448, wi3 = htid + 672;

    float4 ra0, ra1, rw0, rw1, rw2, rw3;
    const float4* A4 = (const float4*)g_att;
    const float4* W4 = (const float4*)W;

    {
        int k0 = kb;
        if (ai0 < NA_F4) { int r = ai0 >> 3, kf = ai0 & 7; ra0 = A4[(size_t)(m0 + r) * (DD/4) + (k0>>2) + kf]; }
        if (ai1 < NA_F4) { int r = ai1 >> 3, kf = ai1 & 7; ra1 = A4[(size_t)(m0 + r) * (DD/4) + (k0>>2) + kf]; }
        if (wi0 < NW_F4) { int kk = wi0 / 25, c = wi0 % 25; rw0 = W4[(size_t)(k0 + kk) * (HH/4) + c]; }
        if (wi1 < NW_F4) { int kk = wi1 / 25, c = wi1 % 25; rw1 = W4[(size_t)(k0 + kk) * (HH/4) + c]; }
        if (wi2 < NW_F4) { int kk = wi2 / 25, c = wi2 % 25; rw2 = W4[(size_t)(k0 + kk) * (HH/4) + c]; }
        if (wi3 < NW_F4) { int kk = wi3 / 25, c = wi3 % 25; rw3 = W4[(size_t)(k0 + kk) * (HH/4) + c]; }
    }

    unsigned long long accP[4][2];
#pragma unroll
    for (int i = 0; i < 4; i++) { accP[i][0] = 0ull; accP[i][1] = 0ull; }

    int rg = htid / 25, cg = htid % 25;
    int rr = rg * 4,  cc = cg * 4;
    bool active = (htid < 200);

    for (int kc = 0; kc < 384; kc += KC) {
        if (ai0 < NA_F4) { int r = ai0 >> 3, kf = (ai0 & 7) * 4;
            sA[half][kf+0][r] = ra0.x; sA[half][kf+1][r] = ra0.y;
            sA[half][kf+2][r] = ra0.z; sA[half][kf+3][r] = ra0.w; }
        if (ai1 < NA_F4) { int r = ai1 >> 3, kf = (ai1 & 7) * 4;
            sA[half][kf+0][r] = ra1.x; sA[half][kf+1][r] = ra1.y;
            sA[half][kf+2][r] = ra1.z; sA[half][kf+3][r] = ra1.w; }
        if (wi0 < NW_F4) { int kk = wi0 / 25, c = (wi0 % 25) * 4; *(float4*)&sW[half][kk][c] = rw0; }
        if (wi1 < NW_F4) { int kk = wi1 / 25, c = (wi1 % 25) * 4; *(float4*)&sW[half][kk][c] = rw1; }
        if (wi2 < NW_F4) { int kk = wi2 / 25, c = (wi2 % 25) * 4; *(float4*)&sW[half][kk][c] = rw2; }
        if (wi3 < NW_F4) { int kk = wi3 / 25, c = (wi3 % 25) * 4; *(float4*)&sW[half][kk][c] = rw3; }
        __syncthreads();

        int kn = kb + kc + KC;
        if (kc + KC < 384) {
            if (ai0 < NA_F4) { int r = ai0 >> 3, kf = ai0 & 7; ra0 = A4[(size_t)(m0 + r) * (DD/4) + (kn>>2) + kf]; }
            if (ai1 < NA_F4) { int r = ai1 >> 3, kf = ai1 & 7; ra1 = A4[(size_t)(m0 + r) * (DD/4) + (kn>>2) + kf]; }
            if (wi0 < NW_F4) { int kk = wi0 / 25, c = wi0 % 25; rw0 = W4[(size_t)(kn + kk) * (HH/4) + c]; }
            if (wi1 < NW_F4) { int kk = wi1 / 25, c = wi1 % 25; rw1 = W4[(size_t)(kn + kk) * (HH/4) + c]; }
            if (wi2 < NW_F4) { int kk = wi2 / 25, c = wi2 % 25; rw2 = W4[(size_t)(kn + kk) * (HH/4) + c]; }
            if (wi3 < NW_F4) { int kk = wi3 / 25, c = wi3 % 25; rw3 = W4[(size_t)(kn + kk) * (HH/4) + c]; }
        }

        if (active) {
#pragma unroll
            for (int kk = 0; kk < KC; kk++) {
                float4 a = *(const float4*)&sA[half][kk][rr];
                float4 w = *(const float4*)&sW[half][kk][cc];
                unsigned long long w01 = f32x2_pack(w.x, w.y);
                unsigned long long w23 = f32x2_pack(w.z, w.w);
                float av[4] = {a.x, a.y, a.z, a.w};
#pragma unroll
                for (int i = 0; i < 4; i++) {
                    unsigned long long ad = f32x2_pack(av[i], av[i]);
                    f32x2_fma(accP[i][0], ad, w01);
                    f32x2_fma(accP[i][1], ad, w23);
                }
            }
        }
        __syncthreads();
    }

    // combine halves through sW[1] (dead after the main loop)
    if (half == 1 && active) {
#pragma unroll
        for (int i = 0; i < 4; i++) {
            float2 p0 = f32x2_unpack(accP[i][0]);
            float2 p1 = f32x2_unpack(accP[i][1]);
            *(float4*)&sW[1][rr + i][cc] = make_float4(p0.x, p0.y, p1.x, p1.y);
        }
    }
    __syncthreads();

    if (half == 0 && active) {
#pragma unroll
        for (int i = 0; i < 4; i++) {
            float2 p0 = f32x2_unpack(accP[i][0]);
            float2 p1 = f32x2_unpack(accP[i][1]);
            float4 o = *(const float4*)&sW[1][rr + i][cc];
            float4 v;
            v.x = tanhf(p0.x + o.x + sB[cc + 0]);
            v.y = tanhf(p0.y + o.y + sB[cc + 1]);
            v.z = tanhf(p1.x + o.z + sB[cc + 2]);
            v.w = tanhf(p1.y + o.w + sB[cc + 3]);
            *(float4*)&out[(size_t)(m0 + rr + i) * HH + cc] = v;
        }
    }
}

extern "C" void kernel_launch(void* const* d_in, const int* in_sizes, int n_in,
                              void* d_out, int out_size) {
    const float* seq   = (const float*)d_in[0];
    const int*   spans = (const int*)d_in[1];
    const int*   mask  = (const int*)d_in[2];
    const float* att_w = (const float*)d_in[3];
    const float* att_b = (const float*)d_in[4];
    const float* ffn_w = (const float*)d_in[5];
    const float* ffn_b = (const float*)d_in[6];
    float*       out   = (float*)d_out;

    k_logits<<<(BB * SS) / 16, 256>>>(seq, att_w, att_b);
    k_span<<<M_TOTAL, 192>>>(seq, spans, mask);
    k_gemm<<<128, 448>>>(ffn_w, ffn_b, out);
}